// round 3
// baseline (speedup 1.0000x reference)
#include <cuda_runtime.h>
#include <math.h>

// Problem constants (fixed by the dataset)
#define B_  32
#define TE_ 8192
#define H_  128

// ---------------- device scratch (no allocations allowed) ----------------
__device__ float g_Uh[B_ * H_];            // U_a . h  per batch  [B,128]
__device__ float g_max[B_];                // softmax max per batch
__device__ float g_inv[B_];                // 1/sum(exp) per batch
__device__ float g_cpart[B_ * 32 * 128];   // partial contexts [b][chunk][h]

// ---------------- K1: Uh[b,k] = sum_h dec[b,h] * U[h,k] ----------------
__global__ void k1_uh(const float* __restrict__ dec, const float* __restrict__ U) {
    __shared__ float d_s[H_];
    int b = blockIdx.x, k = threadIdx.x;
    d_s[k] = dec[b * H_ + k];
    __syncthreads();
    float acc = 0.f;
#pragma unroll 16
    for (int h = 0; h < H_; ++h) acc = fmaf(d_s[h], U[h * H_ + k], acc);
    g_Uh[b * H_ + k] = acc;
}

// ---------------- packed fp32 helpers (sm_103a f32x2 pipe) ----------------
__device__ __forceinline__ unsigned long long dup2(float x) {
    unsigned long long r;
    unsigned u = __float_as_uint(x);
    asm("mov.b64 %0, {%1, %1};" : "=l"(r) : "r"(u));
    return r;
}
__device__ __forceinline__ void ffma2(unsigned long long& d, unsigned long long a,
                                      unsigned long long b) {
    // d = a * b + d  (two packed fp32 FMAs, exact fp32 rounding)
    asm("fma.rn.f32x2 %0, %1, %2, %0;" : "+l"(d) : "l"(a), "l"(b));
}

// ---------------- K2: raw scores = V . tanh(enc@W + Uh) ----------------
// Block: 256 threads = 16(tx: k-groups) x 16(ty: t-groups); 128 timesteps/block.
// Each thread owns an 8t x 8k fp32 accumulator tile, k paired for FFMA2.
// h is processed in 4 chunks of 32 so smem stays <48KB static (2 CTAs/SM).
__global__ void __launch_bounds__(256, 2)
k2_scores(const float* __restrict__ enc, const float* __restrict__ W,
          const float* __restrict__ V, float* __restrict__ scores) {
    __shared__ float W_s[32 * 128];   // [hh][k]
    __shared__ float E_s[128 * 32];   // [t][hh]
    __shared__ float Uh_s[128];
    __shared__ float V_s[128];

    int tid = threadIdx.x;
    int b   = blockIdx.y;
    int t0  = blockIdx.x * 128;
    int tx  = tid & 15;      // k-group: columns tx*8 .. tx*8+7
    int ty  = tid >> 4;      // t-group: rows    ty*8 .. ty*8+7

    if (tid < 128) {
        Uh_s[tid] = g_Uh[b * 128 + tid];
        V_s[tid]  = V[tid];
    }

    const float* encb = enc + ((size_t)b * TE_ + t0) * H_;

    unsigned long long acc[8][4];
#pragma unroll
    for (int i = 0; i < 8; ++i)
#pragma unroll
        for (int j = 0; j < 4; ++j) acc[i][j] = 0ull;

    for (int c = 0; c < 4; ++c) {
        // load W chunk (rows c*32..c*32+31, k contiguous) — straight float4 copy
        for (int i = tid * 4; i < 4096; i += 1024)
            *(float4*)&W_s[i] = *(const float4*)&W[c * 4096 + i];
        // load enc chunk as [t][hh]
        for (int i = tid * 4; i < 4096; i += 1024) {
            int t  = i >> 5;
            int hh = i & 31;
            *(float4*)&E_s[t * 32 + hh] = *(const float4*)&encb[t * 128 + c * 32 + hh];
        }
        __syncthreads();

#pragma unroll 8
        for (int hh = 0; hh < 32; ++hh) {
            ulonglong2 w01 = *(const ulonglong2*)&W_s[hh * 128 + tx * 8];
            ulonglong2 w23 = *(const ulonglong2*)&W_s[hh * 128 + tx * 8 + 4];
#pragma unroll
            for (int i = 0; i < 8; ++i) {
                unsigned long long e = dup2(E_s[(ty * 8 + i) * 32 + hh]);
                ffma2(acc[i][0], e, w01.x);
                ffma2(acc[i][1], e, w01.y);
                ffma2(acc[i][2], e, w23.x);
                ffma2(acc[i][3], e, w23.y);
            }
        }
        __syncthreads();
    }

    // epilogue: s[t] = sum_k V[k] * tanh(y[t,k] + Uh[k]); reduce over the 16 tx lanes
#pragma unroll
    for (int i = 0; i < 8; ++i) {
        float s = 0.f;
#pragma unroll
        for (int j = 0; j < 4; ++j) {
            int k = tx * 8 + 2 * j;
            float lo = __uint_as_float((unsigned)(acc[i][j] & 0xffffffffull));
            float hi = __uint_as_float((unsigned)(acc[i][j] >> 32));
            s += V_s[k]     * tanhf(lo + Uh_s[k]);
            s += V_s[k + 1] * tanhf(hi + Uh_s[k + 1]);
        }
        // xor-shuffle over masks 8,4,2,1 reduces within each 16-lane half-warp
#pragma unroll
        for (int m = 8; m; m >>= 1) s += __shfl_xor_sync(0xffffffffu, s, m);
        if (tx == 0)
            scores[(size_t)b * TE_ + t0 + ty * 8 + i] = s;
    }
}

// ---------------- K3: per-batch softmax stats (max, 1/sum) ----------------
__global__ void k3_stats(const float* __restrict__ scores) {
    __shared__ float red[8];
    int b = blockIdx.x, tid = threadIdx.x;  // 256 threads
    const float* s = scores + (size_t)b * TE_;

    float mx = -3.4e38f;
    for (int i = tid; i < TE_; i += 256) mx = fmaxf(mx, s[i]);
#pragma unroll
    for (int m = 16; m; m >>= 1) mx = fmaxf(mx, __shfl_xor_sync(0xffffffffu, mx, m));
    if ((tid & 31) == 0) red[tid >> 5] = mx;
    __syncthreads();
    if (tid == 0) {
        float m = red[0];
#pragma unroll
        for (int i = 1; i < 8; ++i) m = fmaxf(m, red[i]);
        red[0] = m;
    }
    __syncthreads();
    mx = red[0];
    __syncthreads();

    float sum = 0.f;
    for (int i = tid; i < TE_; i += 256) sum += expf(s[i] - mx);
#pragma unroll
    for (int m = 16; m; m >>= 1) sum += __shfl_xor_sync(0xffffffffu, sum, m);
    if ((tid & 31) == 0) red[tid >> 5] = sum;
    __syncthreads();
    if (tid == 0) {
        float t = 0.f;
#pragma unroll
        for (int i = 0; i < 8; ++i) t += red[i];
        g_max[b] = mx;
        g_inv[b] = 1.f / t;
    }
}

// ---------------- K4: e = softmax(scores) in place + partial contexts ----------------
// Block handles 256 timesteps of one batch; partial context -> g_cpart (deterministic).
__global__ void k4_ctx(const float* __restrict__ enc, float* __restrict__ e_out) {
    __shared__ float e_s[256];
    __shared__ float cpart[128];
    int b   = blockIdx.y;
    int t0  = blockIdx.x * 256;
    int tid = threadIdx.x;  // 256

    float mx  = g_max[b];
    float inv = g_inv[b];

    float* srow = e_out + (size_t)b * TE_ + t0;
    float e = expf(srow[tid] - mx) * inv;
    e_s[tid]  = e;
    srow[tid] = e;  // overwrite raw score with normalized weight
    __syncthreads();

    int h    = tid & 127;
    int half = tid >> 7;  // 0 or 1 -> handles 128 timesteps each
    const float* ep = enc + ((size_t)b * TE_ + t0 + half * 128) * H_ + h;
    float acc = 0.f;
#pragma unroll 8
    for (int t = 0; t < 128; ++t)
        acc = fmaf(e_s[half * 128 + t], ep[t * H_], acc);

    if (half == 0) cpart[h] = acc;
    __syncthreads();
    if (half == 1)
        g_cpart[((size_t)b * 32 + blockIdx.x) * 128 + h] = acc + cpart[h];
}

// ---------------- K5: reduce partial contexts -> c[b,h] ----------------
__global__ void k5_reduce(float* __restrict__ c_out) {
    int b = blockIdx.x, h = threadIdx.x;  // 128 threads
    float s = 0.f;
#pragma unroll
    for (int c = 0; c < 32; ++c) s += g_cpart[((size_t)b * 32 + c) * 128 + h];
    c_out[b * H_ + h] = s;
}

// ---------------- launch ----------------
extern "C" void kernel_launch(void* const* d_in, const int* in_sizes, int n_in,
                              void* d_out, int out_size) {
    const float* enc = (const float*)d_in[0];  // [B, TE, H]
    const float* dec = (const float*)d_in[1];  // [B, 1, H]
    const float* W   = (const float*)d_in[2];  // [H, H]
    const float* U   = (const float*)d_in[3];  // [H, H]
    const float* V   = (const float*)d_in[4];  // [H, 1]

    float* out   = (float*)d_out;
    float* e_out = out;                        // [B, TE]
    float* c_out = out + (size_t)B_ * TE_;     // [B, H]

    k1_uh<<<B_, H_>>>(dec, U);
    k2_scores<<<dim3(TE_ / 128, B_), 256>>>(enc, W, V, e_out);
    k3_stats<<<B_, 256>>>(e_out);
    k4_ctx<<<dim3(TE_ / 256, B_), 256>>>(enc, e_out);
    k5_reduce<<<B_, H_>>>(c_out);
}

// round 10
// speedup vs baseline: 1.3963x; 1.3963x over previous
#include <cuda_runtime.h>
#include <cuda_bf16.h>
#include <math.h>
#include <stdint.h>

#define B_  32
#define TE_ 8192
#define H_  128

// ---------------- device scratch ----------------
__device__ float g_Uh[B_ * H_];
__device__ float g_max[B_];
__device__ float g_inv[B_];
__device__ float g_cpart[B_ * 32 * 128];
__device__ __nv_bfloat16 g_WhiT[H_ * H_];   // W^T split-high  [n=k_out][h]
__device__ __nv_bfloat16 g_WloT[H_ * H_];   // W^T split-low   [n=k_out][h]

// ---------------- helpers ----------------
__device__ __forceinline__ uint32_t smem_u32(const void* p) {
    uint32_t a;
    asm("{ .reg .u64 t; cvta.to.shared.u64 t, %1; cvt.u32.u64 %0, t; }" : "=r"(a) : "l"(p));
    return a;
}
__device__ __forceinline__ void ldsm_x4(uint32_t& r0, uint32_t& r1, uint32_t& r2,
                                        uint32_t& r3, uint32_t addr) {
    asm volatile("ldmatrix.sync.aligned.m8n8.x4.shared.b16 {%0,%1,%2,%3}, [%4];"
                 : "=r"(r0), "=r"(r1), "=r"(r2), "=r"(r3) : "r"(addr));
}
__device__ __forceinline__ void mma_bf16(float* c, uint32_t a0, uint32_t a1,
                                         uint32_t a2, uint32_t a3,
                                         uint32_t b0, uint32_t b1) {
    asm volatile(
        "mma.sync.aligned.m16n8k16.row.col.f32.bf16.bf16.f32 "
        "{%0,%1,%2,%3}, {%4,%5,%6,%7}, {%8,%9}, {%0,%1,%2,%3};"
        : "+f"(c[0]), "+f"(c[1]), "+f"(c[2]), "+f"(c[3])
        : "r"(a0), "r"(a1), "r"(a2), "r"(a3), "r"(b0), "r"(b1));
}
__device__ __forceinline__ float tanh_fast(float x) {
    return 1.0f - __fdividef(2.0f, 1.0f + __expf(2.0f * x));
}

// ---------------- K0: W^T split into bf16 hi/lo ----------------
__global__ void k0_prep(const float* __restrict__ W) {
    int idx = blockIdx.x * 256 + threadIdx.x;      // 16384 total
    int k = idx >> 7, h = idx & 127;
    float x = W[h * H_ + k];
    __nv_bfloat16 hi = __float2bfloat16(x);
    __nv_bfloat16 lo = __float2bfloat16(x - __bfloat162float(hi));
    g_WhiT[k * H_ + h] = hi;
    g_WloT[k * H_ + h] = lo;
}

// ---------------- K1: Uh = dec @ U ----------------
__global__ void k1_uh(const float* __restrict__ dec, const float* __restrict__ U) {
    __shared__ float d_s[H_];
    int b = blockIdx.x, k = threadIdx.x;
    d_s[k] = dec[b * H_ + k];
    __syncthreads();
    float acc = 0.f;
#pragma unroll 16
    for (int h = 0; h < H_; ++h) acc = fmaf(d_s[h], U[h * H_ + k], acc);
    g_Uh[b * H_ + k] = acc;
}

// ---------------- K2: mma.sync split-bf16 GEMM + tanh + V-dot ----------------
// smem rows padded: 128 bf16 + 8 pad = 136 elems = 272 bytes (conflict-free ldmatrix)
#define RSTR     272
#define TILE_B   (128 * RSTR)            // 34816
#define OFF_UH   0
#define OFF_V    512
#define OFF_EPI  1024                    // 2 x 128 floats
#define OFF_AHI  2048
#define OFF_ALO  (OFF_AHI + TILE_B)
#define OFF_BHI  (OFF_ALO + TILE_B)
#define OFF_BLO  (OFF_BHI + TILE_B)
#define K2_SMEM  (OFF_BLO + TILE_B)      // 141312 bytes

__global__ void __launch_bounds__(256, 1)
k2_scores(const float* __restrict__ enc, const float* __restrict__ V,
          float* __restrict__ scores) {
    extern __shared__ char sm[];
    uint32_t base = smem_u32(sm);

    int tid  = threadIdx.x;
    int wid  = tid >> 5;
    int lane = tid & 31;
    int b    = blockIdx.y;
    int t0   = blockIdx.x * 128;

    float* uh_s = (float*)(sm + OFF_UH);
    float* v_s  = (float*)(sm + OFF_V);
    float* epi  = (float*)(sm + OFF_EPI);
    if (tid < 128) {
        uh_s[tid] = g_Uh[b * 128 + tid];
        v_s[tid]  = V[tid];
    }

    // --- load + split-convert enc tile [128 t x 128 h] fp32 -> A_hi/A_lo
    const float4* encb = (const float4*)(enc + ((size_t)b * TE_ + t0) * H_);
#pragma unroll
    for (int i = 0; i < 16; ++i) {
        int g   = i * 256 + tid;            // float4 chunk over 128 x 32
        int row = g >> 5, c4 = g & 31;
        float4 f = encb[g];
        __nv_bfloat16 h0 = __float2bfloat16(f.x), h1 = __float2bfloat16(f.y);
        __nv_bfloat16 h2 = __float2bfloat16(f.z), h3 = __float2bfloat16(f.w);
        __nv_bfloat16 l0 = __float2bfloat16(f.x - __bfloat162float(h0));
        __nv_bfloat16 l1 = __float2bfloat16(f.y - __bfloat162float(h1));
        __nv_bfloat16 l2 = __float2bfloat16(f.z - __bfloat162float(h2));
        __nv_bfloat16 l3 = __float2bfloat16(f.w - __bfloat162float(h3));
        uint2 hp, lp;
        hp.x = (uint32_t)__bfloat16_as_ushort(h0) | ((uint32_t)__bfloat16_as_ushort(h1) << 16);
        hp.y = (uint32_t)__bfloat16_as_ushort(h2) | ((uint32_t)__bfloat16_as_ushort(h3) << 16);
        lp.x = (uint32_t)__bfloat16_as_ushort(l0) | ((uint32_t)__bfloat16_as_ushort(l1) << 16);
        lp.y = (uint32_t)__bfloat16_as_ushort(l2) | ((uint32_t)__bfloat16_as_ushort(l3) << 16);
        int off = row * RSTR + c4 * 8;
        *(uint2*)(sm + OFF_AHI + off) = hp;
        *(uint2*)(sm + OFF_ALO + off) = lp;
    }

    // --- copy W^T hi/lo bf16 tiles (8B chunks)
#pragma unroll
    for (int i = 0; i < 16; ++i) {
        int g   = i * 256 + tid;
        int row = g >> 5, c = g & 31;
        int off = row * RSTR + c * 8;
        *(uint2*)(sm + OFF_BHI + off) = *(const uint2*)(g_WhiT + row * 128 + c * 4);
        *(uint2*)(sm + OFF_BLO + off) = *(const uint2*)(g_WloT + row * 128 + c * 4);
    }
    __syncthreads();

    // warp grid: wy in 0..3 owns rows wy*32..+32; wx in 0..1 owns cols wx*64..+64
    int wy = wid & 3, wx = wid >> 2;

    // ldmatrix per-lane address offsets
    uint32_t aOff = (uint32_t)((lane & 15) * RSTR + (lane >> 4) * 16);
    uint32_t bOff = (uint32_t)(((lane & 7) + ((lane >> 4) << 3)) * RSTR + (((lane >> 3) & 1) << 4));

    uint32_t aHi = base + OFF_AHI + wy * 32 * RSTR + aOff;
    uint32_t aLo = base + OFF_ALO + wy * 32 * RSTR + aOff;
    uint32_t bHi = base + OFF_BHI + wx * 64 * RSTR + bOff;
    uint32_t bLo = base + OFF_BLO + wx * 64 * RSTR + bOff;

    float c[2][8][4];
#pragma unroll
    for (int m = 0; m < 2; ++m)
#pragma unroll
        for (int n = 0; n < 8; ++n)
#pragma unroll
            for (int j = 0; j < 4; ++j) c[m][n][j] = 0.f;

#pragma unroll
    for (int k = 0; k < 8; ++k) {
        uint32_t kb = k * 32;               // 16 bf16 = 32 bytes
        uint32_t bh[4][4], bl[4][4];
#pragma unroll
        for (int p = 0; p < 4; ++p) {
            ldsm_x4(bh[p][0], bh[p][1], bh[p][2], bh[p][3], bHi + p * 16 * RSTR + kb);
            ldsm_x4(bl[p][0], bl[p][1], bl[p][2], bl[p][3], bLo + p * 16 * RSTR + kb);
        }
#pragma unroll
        for (int m = 0; m < 2; ++m) {
            uint32_t ah0, ah1, ah2, ah3, al0, al1, al2, al3;
            ldsm_x4(ah0, ah1, ah2, ah3, aHi + m * 16 * RSTR + kb);
            ldsm_x4(al0, al1, al2, al3, aLo + m * 16 * RSTR + kb);
#pragma unroll
            for (int p = 0; p < 4; ++p) {
                mma_bf16(c[m][2 * p],     ah0, ah1, ah2, ah3, bh[p][0], bh[p][1]);
                mma_bf16(c[m][2 * p + 1], ah0, ah1, ah2, ah3, bh[p][2], bh[p][3]);
                mma_bf16(c[m][2 * p],     ah0, ah1, ah2, ah3, bl[p][0], bl[p][1]);
                mma_bf16(c[m][2 * p + 1], ah0, ah1, ah2, ah3, bl[p][2], bl[p][3]);
                mma_bf16(c[m][2 * p],     al0, al1, al2, al3, bh[p][0], bh[p][1]);
                mma_bf16(c[m][2 * p + 1], al0, al1, al2, al3, bh[p][2], bh[p][3]);
            }
        }
    }

    // --- epilogue: s[t] += v[n] * tanh(y + uh[n]); reduce lanes %4, then wx halves
    int qid = lane >> 2;                    // row within 8-row group
    int npair = (lane & 3) * 2;
#pragma unroll
    for (int m = 0; m < 2; ++m) {
        float s0 = 0.f, s1 = 0.f;
#pragma unroll
        for (int nt = 0; nt < 8; ++nt) {
            int n = wx * 64 + nt * 8 + npair;
            float vn0 = v_s[n], vn1 = v_s[n + 1];
            float u0 = uh_s[n], u1 = uh_s[n + 1];
            s0 += vn0 * tanh_fast(c[m][nt][0] + u0) + vn1 * tanh_fast(c[m][nt][1] + u1);
            s1 += vn0 * tanh_fast(c[m][nt][2] + u0) + vn1 * tanh_fast(c[m][nt][3] + u1);
        }
        s0 += __shfl_xor_sync(0xffffffffu, s0, 1);
        s0 += __shfl_xor_sync(0xffffffffu, s0, 2);
        s1 += __shfl_xor_sync(0xffffffffu, s1, 1);
        s1 += __shfl_xor_sync(0xffffffffu, s1, 2);
        if ((lane & 3) == 0) {
            int r = wy * 32 + m * 16 + qid;
            epi[wx * 128 + r]     = s0;
            epi[wx * 128 + r + 8] = s1;
        }
    }
    __syncthreads();
    if (tid < 128)
        scores[(size_t)b * TE_ + t0 + tid] = epi[tid] + epi[128 + tid];
}

// ---------------- K3: per-batch softmax stats ----------------
__global__ void k3_stats(const float* __restrict__ scores) {
    __shared__ float red[8];
    int b = blockIdx.x, tid = threadIdx.x;
    const float* s = scores + (size_t)b * TE_;

    float mx = -3.4e38f;
    for (int i = tid; i < TE_; i += 256) mx = fmaxf(mx, s[i]);
#pragma unroll
    for (int m = 16; m; m >>= 1) mx = fmaxf(mx, __shfl_xor_sync(0xffffffffu, mx, m));
    if ((tid & 31) == 0) red[tid >> 5] = mx;
    __syncthreads();
    if (tid == 0) {
        float m = red[0];
#pragma unroll
        for (int i = 1; i < 8; ++i) m = fmaxf(m, red[i]);
        red[0] = m;
    }
    __syncthreads();
    mx = red[0];
    __syncthreads();

    float sum = 0.f;
    for (int i = tid; i < TE_; i += 256) sum += expf(s[i] - mx);
#pragma unroll
    for (int m = 16; m; m >>= 1) sum += __shfl_xor_sync(0xffffffffu, sum, m);
    if ((tid & 31) == 0) red[tid >> 5] = sum;
    __syncthreads();
    if (tid == 0) {
        float t = 0.f;
#pragma unroll
        for (int i = 0; i < 8; ++i) t += red[i];
        g_max[b] = mx;
        g_inv[b] = 1.f / t;
    }
}

// ---------------- K4: normalize e in place + partial contexts (float4) ----------------
__global__ void k4_ctx(const float* __restrict__ enc, float* __restrict__ e_out) {
    __shared__ float e_s[256];
    __shared__ float cp[8 * 128];
    int b = blockIdx.y, t0 = blockIdx.x * 256, tid = threadIdx.x;

    float mx = g_max[b], inv = g_inv[b];
    float* srow = e_out + (size_t)b * TE_ + t0;
    float e = expf(srow[tid] - mx) * inv;
    e_s[tid]  = e;
    srow[tid] = e;
    __syncthreads();

    int h4 = tid & 31, slice = tid >> 5;       // slice handles 32 timesteps
    const float4* ep = (const float4*)(enc + ((size_t)b * TE_ + t0 + slice * 32) * H_) + h4;
    float4 acc = {0.f, 0.f, 0.f, 0.f};
#pragma unroll
    for (int t = 0; t < 32; ++t) {
        float w = e_s[slice * 32 + t];
        float4 v = ep[(size_t)t * 32];
        acc.x = fmaf(w, v.x, acc.x);
        acc.y = fmaf(w, v.y, acc.y);
        acc.z = fmaf(w, v.z, acc.z);
        acc.w = fmaf(w, v.w, acc.w);
    }
    *(float4*)&cp[slice * 128 + h4 * 4] = acc;
    __syncthreads();
    if (tid < 128) {
        float s = 0.f;
#pragma unroll
        for (int sl = 0; sl < 8; ++sl) s += cp[sl * 128 + tid];
        g_cpart[((size_t)b * 32 + blockIdx.x) * 128 + tid] = s;
    }
}

// ---------------- K5: reduce partial contexts ----------------
__global__ void k5_reduce(float* __restrict__ c_out) {
    int b = blockIdx.x, h = threadIdx.x;
    float s = 0.f;
#pragma unroll
    for (int c = 0; c < 32; ++c) s += g_cpart[((size_t)b * 32 + c) * 128 + h];
    c_out[b * H_ + h] = s;
}

// ---------------- launch ----------------
extern "C" void kernel_launch(void* const* d_in, const int* in_sizes, int n_in,
                              void* d_out, int out_size) {
    const float* enc = (const float*)d_in[0];
    const float* dec = (const float*)d_in[1];
    const float* W   = (const float*)d_in[2];
    const float* U   = (const float*)d_in[3];
    const float* V   = (const float*)d_in[4];

    float* out   = (float*)d_out;
    float* e_out = out;
    float* c_out = out + (size_t)B_ * TE_;

    static int s_attr_done = 0;
    if (!s_attr_done) {
        cudaFuncSetAttribute(k2_scores, cudaFuncAttributeMaxDynamicSharedMemorySize, K2_SMEM);
        s_attr_done = 1;
    }

    k0_prep<<<64, 256>>>(W);
    k1_uh<<<B_, H_>>>(dec, U);
    k2_scores<<<dim3(TE_ / 128, B_), 256, K2_SMEM>>>(enc, V, e_out);
    k3_stats<<<B_, 256>>>(e_out);
    k4_ctx<<<dim3(TE_ / 256, B_), 256>>>(enc, e_out);
    k5_reduce<<<B_, H_>>>(c_out);
}

// round 12
// speedup vs baseline: 2.2574x; 1.6167x over previous
#include <cuda_runtime.h>
#include <cuda_bf16.h>
#include <math.h>
#include <stdint.h>

#define B_  32
#define TE_ 8192
#define H_  128
#define NTILE 2048            // (B_*TE_)/128 tiles of 128 timesteps
#define TPB   64              // tiles per batch

// ---------------- device scratch ----------------
__device__ float g_Uh[B_ * H_];
__device__ float g_max[B_];
__device__ float g_inv[B_];
__device__ float g_tmax[NTILE];            // per-tile max
__device__ float g_tsum[NTILE];            // per-tile sum(exp(s - tmax))
__device__ float g_cpart[NTILE * H_];      // exp-weighted partial contexts
__device__ __nv_bfloat16 g_WhiT[H_ * H_];  // W^T split-high [n][h]
__device__ __nv_bfloat16 g_WloT[H_ * H_];  // W^T split-low  [n][h]

// ---------------- helpers ----------------
__device__ __forceinline__ uint32_t smem_u32(const void* p) {
    uint32_t a;
    asm("{ .reg .u64 t; cvta.to.shared.u64 t, %1; cvt.u32.u64 %0, t; }" : "=r"(a) : "l"(p));
    return a;
}
__device__ __forceinline__ void ldsm_x4(uint32_t& r0, uint32_t& r1, uint32_t& r2,
                                        uint32_t& r3, uint32_t addr) {
    asm volatile("ldmatrix.sync.aligned.m8n8.x4.shared.b16 {%0,%1,%2,%3}, [%4];"
                 : "=r"(r0), "=r"(r1), "=r"(r2), "=r"(r3) : "r"(addr));
}
__device__ __forceinline__ void mma_bf16(float* c, uint32_t a0, uint32_t a1,
                                         uint32_t a2, uint32_t a3,
                                         uint32_t b0, uint32_t b1) {
    asm volatile(
        "mma.sync.aligned.m16n8k16.row.col.f32.bf16.bf16.f32 "
        "{%0,%1,%2,%3}, {%4,%5,%6,%7}, {%8,%9}, {%0,%1,%2,%3};"
        : "+f"(c[0]), "+f"(c[1]), "+f"(c[2]), "+f"(c[3])
        : "r"(a0), "r"(a1), "r"(a2), "r"(a3), "r"(b0), "r"(b1));
}
__device__ __forceinline__ float tanh_fast(float x) {
    return 1.0f - __fdividef(2.0f, 1.0f + __expf(2.0f * x));
}

// ---------------- K0: W^T split into bf16 hi/lo ----------------
__global__ void k0_prep(const float* __restrict__ W) {
    int idx = blockIdx.x * 256 + threadIdx.x;   // 16384
    int k = idx >> 7, h = idx & 127;
    float x = W[h * H_ + k];
    __nv_bfloat16 hi = __float2bfloat16(x);
    __nv_bfloat16 lo = __float2bfloat16(x - __bfloat162float(hi));
    g_WhiT[k * H_ + h] = hi;
    g_WloT[k * H_ + h] = lo;
}

// ---------------- K1: Uh = dec @ U ----------------
__global__ void k1_uh(const float* __restrict__ dec, const float* __restrict__ U) {
    __shared__ float d_s[H_];
    int b = blockIdx.x, k = threadIdx.x;
    d_s[k] = dec[b * H_ + k];
    __syncthreads();
    float acc = 0.f;
#pragma unroll 16
    for (int h = 0; h < H_; ++h) acc = fmaf(d_s[h], U[h * H_ + k], acc);
    g_Uh[b * H_ + k] = acc;
}

// ---------------- K2: persistent fused GEMM + tanh·V + online softmax + context ----------------
#define RSTR     272                      // 128 bf16 + 8 pad = 272 B rows
#define TILE_B   (128 * RSTR)             // 34816
#define OFF_UH   0
#define OFF_V    512
#define OFF_EPI  1024                     // 2 x 128 floats
#define OFF_SW   2048                     // 128 floats: s then w
#define OFF_RED  2560                     // 8 floats
#define OFF_CP   2624                     // 4 x 128 floats
#define OFF_AHI  4864                     // 16B aligned
#define OFF_ALO  (OFF_AHI + TILE_B)
#define OFF_BHI  (OFF_ALO + TILE_B)
#define OFF_BLO  (OFF_BHI + TILE_B)
#define K2_SMEM  (OFF_BLO + TILE_B)       // 144128 B

__global__ void __launch_bounds__(512, 1)
k2_scores(const float* __restrict__ enc, const float* __restrict__ V,
          float* __restrict__ scores) {
    extern __shared__ char sm[];
    uint32_t base = smem_u32(sm);

    int tid  = threadIdx.x;
    int wid  = tid >> 5;
    int lane = tid & 31;

    float* uh_s = (float*)(sm + OFF_UH);
    float* v_s  = (float*)(sm + OFF_V);
    float* epi  = (float*)(sm + OFF_EPI);
    float* sw   = (float*)(sm + OFF_SW);
    float* red  = (float*)(sm + OFF_RED);
    float* cp   = (float*)(sm + OFF_CP);

    if (tid < 128) v_s[tid] = V[tid];

    // W tiles: loaded ONCE per CTA (invariant across tiles)
#pragma unroll
    for (int i = 0; i < 8; ++i) {
        int g = i * 512 + tid;              // 8B chunk over 128 x 128 bf16
        int row = g >> 5, c = g & 31;
        int off = row * RSTR + c * 8;
        *(uint2*)(sm + OFF_BHI + off) = *(const uint2*)(g_WhiT + row * 128 + c * 4);
        *(uint2*)(sm + OFF_BLO + off) = *(const uint2*)(g_WloT + row * 128 + c * 4);
    }

    // warp grid: wy = wid&7 -> rows wy*16..+16 ; wx = wid>>3 -> cols wx*64..+64
    int wy = wid & 7, wx = wid >> 3;
    uint32_t aOff = (uint32_t)((lane & 15) * RSTR + (lane >> 4) * 16);
    uint32_t bOff = (uint32_t)(((lane & 7) + ((lane >> 4) << 3)) * RSTR + (((lane >> 3) & 1) << 4));
    uint32_t aHi = base + OFF_AHI + wy * 16 * RSTR + aOff;
    uint32_t aLo = base + OFF_ALO + wy * 16 * RSTR + aOff;
    uint32_t bHi = base + OFF_BHI + wx * 64 * RSTR + bOff;
    uint32_t bLo = base + OFF_BLO + wx * 64 * RSTR + bOff;

    int T = blockIdx.x;
    bool valid = (T < NTILE);
    float4 f[8];
    if (valid) {
        const float4* encT = (const float4*)(enc + (size_t)T * 128 * H_);
#pragma unroll
        for (int i = 0; i < 8; ++i) f[i] = encT[i * 512 + tid];
    }

    while (valid) {
        int b  = T >> 6;
        int ti = T & 63;

        __syncthreads();   // A smem + epi free from previous tile

        // convert staged fp32 -> bf16 hi/lo into A tiles
#pragma unroll
        for (int i = 0; i < 8; ++i) {
            int g = i * 512 + tid;
            int row = g >> 5, c4 = g & 31;
            float4 ff = f[i];
            __nv_bfloat16 h0 = __float2bfloat16(ff.x), h1 = __float2bfloat16(ff.y);
            __nv_bfloat16 h2 = __float2bfloat16(ff.z), h3 = __float2bfloat16(ff.w);
            __nv_bfloat16 l0 = __float2bfloat16(ff.x - __bfloat162float(h0));
            __nv_bfloat16 l1 = __float2bfloat16(ff.y - __bfloat162float(h1));
            __nv_bfloat16 l2 = __float2bfloat16(ff.z - __bfloat162float(h2));
            __nv_bfloat16 l3 = __float2bfloat16(ff.w - __bfloat162float(h3));
            uint2 hp, lp;
            hp.x = (uint32_t)__bfloat16_as_ushort(h0) | ((uint32_t)__bfloat16_as_ushort(h1) << 16);
            hp.y = (uint32_t)__bfloat16_as_ushort(h2) | ((uint32_t)__bfloat16_as_ushort(h3) << 16);
            lp.x = (uint32_t)__bfloat16_as_ushort(l0) | ((uint32_t)__bfloat16_as_ushort(l1) << 16);
            lp.y = (uint32_t)__bfloat16_as_ushort(l2) | ((uint32_t)__bfloat16_as_ushort(l3) << 16);
            int off = row * RSTR + c4 * 8;
            *(uint2*)(sm + OFF_AHI + off) = hp;
            *(uint2*)(sm + OFF_ALO + off) = lp;
        }
        if (tid < 128) uh_s[tid] = g_Uh[b * 128 + tid];
        __syncthreads();

        // prefetch NEXT tile while MMA runs
        int Tn = T + gridDim.x;
        bool nvalid = (Tn < NTILE);
        if (nvalid) {
            const float4* encT = (const float4*)(enc + (size_t)Tn * 128 * H_);
#pragma unroll
            for (int i = 0; i < 8; ++i) f[i] = encT[i * 512 + tid];
        }

        // ---- MMA: 16 rows x 64 cols per warp, 3-term split-bf16
        float c[8][4];
#pragma unroll
        for (int n = 0; n < 8; ++n)
#pragma unroll
            for (int j = 0; j < 4; ++j) c[n][j] = 0.f;

#pragma unroll
        for (int k = 0; k < 8; ++k) {
            uint32_t kb = k * 32;
            uint32_t bh[4][4], bl[4][4];
#pragma unroll
            for (int p = 0; p < 4; ++p) {
                ldsm_x4(bh[p][0], bh[p][1], bh[p][2], bh[p][3], bHi + p * 16 * RSTR + kb);
                ldsm_x4(bl[p][0], bl[p][1], bl[p][2], bl[p][3], bLo + p * 16 * RSTR + kb);
            }
            uint32_t ah0, ah1, ah2, ah3, al0, al1, al2, al3;
            ldsm_x4(ah0, ah1, ah2, ah3, aHi + kb);
            ldsm_x4(al0, al1, al2, al3, aLo + kb);
#pragma unroll
            for (int p = 0; p < 4; ++p) {
                mma_bf16(c[2 * p],     ah0, ah1, ah2, ah3, bh[p][0], bh[p][1]);
                mma_bf16(c[2 * p + 1], ah0, ah1, ah2, ah3, bh[p][2], bh[p][3]);
                mma_bf16(c[2 * p],     ah0, ah1, ah2, ah3, bl[p][0], bl[p][1]);
                mma_bf16(c[2 * p + 1], ah0, ah1, ah2, ah3, bl[p][2], bl[p][3]);
                mma_bf16(c[2 * p],     al0, al1, al2, al3, bh[p][0], bh[p][1]);
                mma_bf16(c[2 * p + 1], al0, al1, al2, al3, bh[p][2], bh[p][3]);
            }
        }

        // ---- epilogue: s[t] = sum_n v[n] * tanh(y + uh[n])
        {
            int qid = lane >> 2;
            int npair = (lane & 3) * 2;
            float s0 = 0.f, s1 = 0.f;
#pragma unroll
            for (int nt = 0; nt < 8; ++nt) {
                int n = wx * 64 + nt * 8 + npair;
                float vn0 = v_s[n], vn1 = v_s[n + 1];
                float u0 = uh_s[n], u1 = uh_s[n + 1];
                s0 += vn0 * tanh_fast(c[nt][0] + u0) + vn1 * tanh_fast(c[nt][1] + u1);
                s1 += vn0 * tanh_fast(c[nt][2] + u0) + vn1 * tanh_fast(c[nt][3] + u1);
            }
            s0 += __shfl_xor_sync(0xffffffffu, s0, 1);
            s0 += __shfl_xor_sync(0xffffffffu, s0, 2);
            s1 += __shfl_xor_sync(0xffffffffu, s1, 1);
            s1 += __shfl_xor_sync(0xffffffffu, s1, 2);
            if ((lane & 3) == 0) {
                int r = wy * 16 + qid;
                epi[wx * 128 + r]     = s0;
                epi[wx * 128 + r + 8] = s1;
            }
        }
        __syncthreads();

        // ---- tile softmax stats: raw score out, tile max, w = exp(s-m), tile sum
        float sv = 0.f;
        if (tid < 128) {
            sv = epi[tid] + epi[128 + tid];
            scores[(size_t)T * 128 + tid] = sv;        // raw score (normalized later)
            float m = sv;
#pragma unroll
            for (int msk = 16; msk; msk >>= 1) m = fmaxf(m, __shfl_xor_sync(0xffffffffu, m, msk));
            if (lane == 0) red[wid] = m;
        }
        __syncthreads();
        float mt = fmaxf(fmaxf(red[0], red[1]), fmaxf(red[2], red[3]));
        if (tid < 128) {
            float w = __expf(sv - mt);
            sw[tid] = w;
#pragma unroll
            for (int msk = 16; msk; msk >>= 1) w += __shfl_xor_sync(0xffffffffu, w, msk);
            if (lane == 0) red[4 + wid] = w;
        }
        __syncthreads();
        if (tid == 0) {
            g_tmax[T] = mt;
            g_tsum[T] = red[4] + red[5] + red[6] + red[7];
        }

        // ---- partial context from resident A tile: cpart[h] = sum_t w[t]*(hi+lo)
        {
            int h = tid & 127;
            int q = tid >> 7;                  // quarter: 32 timesteps each
            const char* pAhi = sm + OFF_AHI + (q * 32) * RSTR + h * 2;
            const char* pAlo = sm + OFF_ALO + (q * 32) * RSTR + h * 2;
            float acc = 0.f;
#pragma unroll 8
            for (int t = 0; t < 32; ++t) {
                float ev = __bfloat162float(*(const __nv_bfloat16*)(pAhi + t * RSTR))
                         + __bfloat162float(*(const __nv_bfloat16*)(pAlo + t * RSTR));
                acc = fmaf(sw[q * 32 + t], ev, acc);
            }
            cp[q * 128 + h] = acc;
        }
        __syncthreads();
        if (tid < 128)
            g_cpart[(size_t)T * 128 + tid] = cp[tid] + cp[128 + tid] + cp[256 + tid] + cp[384 + tid];

        T = Tn;
        valid = nvalid;
        (void)ti;
    }
}

// ---------------- K3: combine per-tile stats -> g_max, g_inv ----------------
__global__ void k3_comb() {
    int b = blockIdx.x, t = threadIdx.x;       // 32 threads
    float m0 = g_tmax[b * TPB + t], m1 = g_tmax[b * TPB + 32 + t];
    float mm = fmaxf(m0, m1);
#pragma unroll
    for (int msk = 16; msk; msk >>= 1) mm = fmaxf(mm, __shfl_xor_sync(0xffffffffu, mm, msk));
    float s = g_tsum[b * TPB + t] * expf(m0 - mm) + g_tsum[b * TPB + 32 + t] * expf(m1 - mm);
#pragma unroll
    for (int msk = 16; msk; msk >>= 1) s += __shfl_xor_sync(0xffffffffu, s, msk);
    if (t == 0) { g_max[b] = mm; g_inv[b] = 1.f / s; }
}

// ---------------- K4: e = exp(s - gmax) * inv (in place, elementwise) ----------------
__global__ void k4_e(float* __restrict__ e_out) {
    int idx = blockIdx.x * 256 + threadIdx.x;  // 262144 total
    int b = idx >> 13;
    e_out[idx] = expf(e_out[idx] - g_max[b]) * g_inv[b];
}

// ---------------- K5: rescale + reduce partial contexts ----------------
__global__ void k5_ctx(float* __restrict__ c_out) {
    __shared__ float sc[TPB];
    int b = blockIdx.x, tid = threadIdx.x;     // 128 threads
    if (tid < TPB) sc[tid] = expf(g_tmax[b * TPB + tid] - g_max[b]);
    __syncthreads();
    float s = 0.f;
#pragma unroll
    for (int ti = 0; ti < TPB; ++ti)
        s += g_cpart[(size_t)(b * TPB + ti) * 128 + tid] * sc[ti];
    c_out[b * H_ + tid] = s * g_inv[b];
}

// ---------------- launch ----------------
extern "C" void kernel_launch(void* const* d_in, const int* in_sizes, int n_in,
                              void* d_out, int out_size) {
    const float* enc = (const float*)d_in[0];
    const float* dec = (const float*)d_in[1];
    const float* W   = (const float*)d_in[2];
    const float* U   = (const float*)d_in[3];
    const float* V   = (const float*)d_in[4];

    float* out   = (float*)d_out;
    float* e_out = out;                        // [B, TE]
    float* c_out = out + (size_t)B_ * TE_;     // [B, H]

    static int s_grid = 0;
    if (!s_grid) {
        int dev = 0, sms = 148;
        cudaGetDevice(&dev);
        cudaDeviceGetAttribute(&sms, cudaDevAttrMultiProcessorCount, dev);
        cudaFuncSetAttribute(k2_scores, cudaFuncAttributeMaxDynamicSharedMemorySize, K2_SMEM);
        s_grid = sms > 0 ? sms : 148;
        if (s_grid > NTILE) s_grid = NTILE;
    }

    k0_prep<<<64, 256>>>(W);
    k1_uh<<<B_, H_>>>(dec, U);
    k2_scores<<<s_grid, 512, K2_SMEM>>>(enc, V, e_out);
    k3_comb<<<B_, 32>>>();
    k4_e<<<1024, 256>>>(e_out);
    k5_ctx<<<B_, 128>>>(c_out);
}

// round 13
// speedup vs baseline: 2.4274x; 1.0753x over previous
#include <cuda_runtime.h>
#include <cuda_bf16.h>
#include <math.h>
#include <stdint.h>

#define B_  32
#define TE_ 8192
#define H_  128
#define NTILE 2048            // (B_*TE_)/128 tiles of 128 timesteps
#define TPB   64              // tiles per batch

// ---------------- device scratch ----------------
__device__ float g_Uh[B_ * H_];
__device__ float g_tmax[NTILE];            // per-tile max
__device__ float g_tsum[NTILE];            // per-tile sum(exp(s - tmax))
__device__ float g_cpart[NTILE * H_];      // exp-weighted partial contexts
__device__ __nv_bfloat16 g_WhiT[H_ * H_];  // W^T split-high [n][h]
__device__ __nv_bfloat16 g_WloT[H_ * H_];  // W^T split-low  [n][h]

// ---------------- helpers ----------------
__device__ __forceinline__ uint32_t smem_u32(const void* p) {
    uint32_t a;
    asm("{ .reg .u64 t; cvta.to.shared.u64 t, %1; cvt.u32.u64 %0, t; }" : "=r"(a) : "l"(p));
    return a;
}
__device__ __forceinline__ void ldsm_x4(uint32_t& r0, uint32_t& r1, uint32_t& r2,
                                        uint32_t& r3, uint32_t addr) {
    asm volatile("ldmatrix.sync.aligned.m8n8.x4.shared.b16 {%0,%1,%2,%3}, [%4];"
                 : "=r"(r0), "=r"(r1), "=r"(r2), "=r"(r3) : "r"(addr));
}
__device__ __forceinline__ void mma_bf16(float* c, uint32_t a0, uint32_t a1,
                                         uint32_t a2, uint32_t a3,
                                         uint32_t b0, uint32_t b1) {
    asm volatile(
        "mma.sync.aligned.m16n8k16.row.col.f32.bf16.bf16.f32 "
        "{%0,%1,%2,%3}, {%4,%5,%6,%7}, {%8,%9}, {%0,%1,%2,%3};"
        : "+f"(c[0]), "+f"(c[1]), "+f"(c[2]), "+f"(c[3])
        : "r"(a0), "r"(a1), "r"(a2), "r"(a3), "r"(b0), "r"(b1));
}
__device__ __forceinline__ float tanh_approx(float x) {
    float y;
    asm("tanh.approx.f32 %0, %1;" : "=f"(y) : "f"(x));
    return y;
}
#define CP_ASYNC16(dst, src) \
    asm volatile("cp.async.cg.shared.global [%0], [%1], 16;" :: "r"(dst), "l"(src))
#define CP_COMMIT()  asm volatile("cp.async.commit_group;" ::: "memory")
#define CP_WAIT0()   asm volatile("cp.async.wait_group 0;" ::: "memory")

// ---------------- K01: W^T hi/lo split (blocks 0..63) + Uh (blocks 64..79) ----------------
__global__ void k01_prep(const float* __restrict__ W, const float* __restrict__ dec,
                         const float* __restrict__ U) {
    int bid = blockIdx.x, tid = threadIdx.x;
    if (bid < 64) {
        int idx = bid * 256 + tid;          // 16384 total
        int k = idx >> 7, h = idx & 127;
        float x = W[h * H_ + k];
        __nv_bfloat16 hi = __float2bfloat16(x);
        __nv_bfloat16 lo = __float2bfloat16(x - __bfloat162float(hi));
        g_WhiT[k * H_ + h] = hi;
        g_WloT[k * H_ + h] = lo;
    } else {
        __shared__ float d_s[2][H_];
        int half = tid >> 7, k = tid & 127;
        int b = (bid - 64) * 2 + half;
        d_s[half][k] = dec[b * H_ + k];
        __syncthreads();
        float acc = 0.f;
#pragma unroll 16
        for (int h = 0; h < H_; ++h) acc = fmaf(d_s[half][h], U[h * H_ + k], acc);
        g_Uh[b * H_ + k] = acc;
    }
}

// ---------------- K2: persistent fused GEMM + tanh·V + online softmax + context ----------------
#define RSTR     272                      // 128 bf16 + 8 pad = 272 B rows
#define TILE_B   (128 * RSTR)             // 34816
#define OFF_UH   0
#define OFF_V    512
#define OFF_EPI  1024                     // 2 x 128 floats
#define OFF_SW   2048                     // 128 floats
#define OFF_RED  2560                     // 8 floats
#define OFF_CP   2624                     // 4 x 128 floats
#define OFF_AHI  4864
#define OFF_ALO  (OFF_AHI + TILE_B)
#define OFF_BHI  (OFF_ALO + TILE_B)
#define OFF_BLO  (OFF_BHI + TILE_B)
#define OFF_STG  (OFF_BLO + TILE_B)       // fp32 stage, 64 KB
#define K2_SMEM  (OFF_STG + 65536)        // 209664 B

__global__ void __launch_bounds__(512, 1)
k2_scores(const float* __restrict__ enc, const float* __restrict__ V,
          float* __restrict__ scores) {
    extern __shared__ char sm[];
    uint32_t base = smem_u32(sm);

    int tid  = threadIdx.x;
    int wid  = tid >> 5;
    int lane = tid & 31;

    float* uh_s = (float*)(sm + OFF_UH);
    float* v_s  = (float*)(sm + OFF_V);
    float* epi  = (float*)(sm + OFF_EPI);
    float* swm  = (float*)(sm + OFF_SW);
    float* red  = (float*)(sm + OFF_RED);
    float* cp   = (float*)(sm + OFF_CP);

    if (tid < 128) v_s[tid] = V[tid];

    // W tiles: loaded ONCE per CTA
#pragma unroll
    for (int i = 0; i < 8; ++i) {
        int g = i * 512 + tid;
        int row = g >> 5, c = g & 31;
        int off = row * RSTR + c * 8;
        *(uint2*)(sm + OFF_BHI + off) = *(const uint2*)(g_WhiT + row * 128 + c * 4);
        *(uint2*)(sm + OFF_BLO + off) = *(const uint2*)(g_WloT + row * 128 + c * 4);
    }

    int wy = wid & 7, wx = wid >> 3;
    uint32_t aOff = (uint32_t)((lane & 15) * RSTR + (lane >> 4) * 16);
    uint32_t bOff = (uint32_t)(((lane & 7) + ((lane >> 4) << 3)) * RSTR + (((lane >> 3) & 1) << 4));
    uint32_t aHi = base + OFF_AHI + wy * 16 * RSTR + aOff;
    uint32_t aLo = base + OFF_ALO + wy * 16 * RSTR + aOff;
    uint32_t bHi = base + OFF_BHI + wx * 64 * RSTR + bOff;
    uint32_t bLo = base + OFF_BLO + wx * 64 * RSTR + bOff;
    uint32_t stg = base + OFF_STG + tid * 16;

    int T = blockIdx.x;
    bool valid = (T < NTILE);
    if (valid) {
        const float4* encT = (const float4*)(enc + (size_t)T * 128 * H_);
#pragma unroll
        for (int i = 0; i < 8; ++i)
            CP_ASYNC16(stg + i * 8192, encT + i * 512 + tid);
        CP_COMMIT();
    }

    while (valid) {
        int b = T >> 6;

        CP_WAIT0();
        __syncthreads();   // stage ready; A tiles free (prev tile's context read done)

        // convert staged fp32 -> bf16 hi/lo A tiles
#pragma unroll
        for (int i = 0; i < 8; ++i) {
            int g = i * 512 + tid;
            int row = g >> 5, c4 = g & 31;
            float4 ff = *(const float4*)(sm + OFF_STG + (size_t)g * 16);
            __nv_bfloat16 h0 = __float2bfloat16(ff.x), h1 = __float2bfloat16(ff.y);
            __nv_bfloat16 h2 = __float2bfloat16(ff.z), h3 = __float2bfloat16(ff.w);
            __nv_bfloat16 l0 = __float2bfloat16(ff.x - __bfloat162float(h0));
            __nv_bfloat16 l1 = __float2bfloat16(ff.y - __bfloat162float(h1));
            __nv_bfloat16 l2 = __float2bfloat16(ff.z - __bfloat162float(h2));
            __nv_bfloat16 l3 = __float2bfloat16(ff.w - __bfloat162float(h3));
            uint2 hp, lp;
            hp.x = (uint32_t)__bfloat16_as_ushort(h0) | ((uint32_t)__bfloat16_as_ushort(h1) << 16);
            hp.y = (uint32_t)__bfloat16_as_ushort(h2) | ((uint32_t)__bfloat16_as_ushort(h3) << 16);
            lp.x = (uint32_t)__bfloat16_as_ushort(l0) | ((uint32_t)__bfloat16_as_ushort(l1) << 16);
            lp.y = (uint32_t)__bfloat16_as_ushort(l2) | ((uint32_t)__bfloat16_as_ushort(l3) << 16);
            int off = row * RSTR + c4 * 8;
            *(uint2*)(sm + OFF_AHI + off) = hp;
            *(uint2*)(sm + OFF_ALO + off) = lp;
        }
        if (tid < 128) uh_s[tid] = g_Uh[b * 128 + tid];
        __syncthreads();   // A ready; stage free

        // prefetch NEXT tile into stage (hidden behind MMA + epilogue)
        int Tn = T + gridDim.x;
        bool nvalid = (Tn < NTILE);
        if (nvalid) {
            const float4* encT = (const float4*)(enc + (size_t)Tn * 128 * H_);
#pragma unroll
            for (int i = 0; i < 8; ++i)
                CP_ASYNC16(stg + i * 8192, encT + i * 512 + tid);
            CP_COMMIT();
        }

        // ---- MMA: 16 rows x 64 cols per warp, 3-term split-bf16
        float c[8][4];
#pragma unroll
        for (int n = 0; n < 8; ++n)
#pragma unroll
            for (int j = 0; j < 4; ++j) c[n][j] = 0.f;

#pragma unroll
        for (int k = 0; k < 8; ++k) {
            uint32_t kb = k * 32;
            uint32_t bh[4][4], bl[4][4];
#pragma unroll
            for (int p = 0; p < 4; ++p) {
                ldsm_x4(bh[p][0], bh[p][1], bh[p][2], bh[p][3], bHi + p * 16 * RSTR + kb);
                ldsm_x4(bl[p][0], bl[p][1], bl[p][2], bl[p][3], bLo + p * 16 * RSTR + kb);
            }
            uint32_t ah0, ah1, ah2, ah3, al0, al1, al2, al3;
            ldsm_x4(ah0, ah1, ah2, ah3, aHi + kb);
            ldsm_x4(al0, al1, al2, al3, aLo + kb);
#pragma unroll
            for (int p = 0; p < 4; ++p) {
                mma_bf16(c[2 * p],     ah0, ah1, ah2, ah3, bh[p][0], bh[p][1]);
                mma_bf16(c[2 * p + 1], ah0, ah1, ah2, ah3, bh[p][2], bh[p][3]);
                mma_bf16(c[2 * p],     ah0, ah1, ah2, ah3, bl[p][0], bl[p][1]);
                mma_bf16(c[2 * p + 1], ah0, ah1, ah2, ah3, bl[p][2], bl[p][3]);
                mma_bf16(c[2 * p],     al0, al1, al2, al3, bh[p][0], bh[p][1]);
                mma_bf16(c[2 * p + 1], al0, al1, al2, al3, bh[p][2], bh[p][3]);
            }
        }

        // ---- epilogue: s[t] = sum_n v[n] * tanh(y + uh[n])
        {
            int qid = lane >> 2;
            int npair = (lane & 3) * 2;
            float s0 = 0.f, s1 = 0.f;
#pragma unroll
            for (int nt = 0; nt < 8; ++nt) {
                int n = wx * 64 + nt * 8 + npair;
                float vn0 = v_s[n], vn1 = v_s[n + 1];
                float u0 = uh_s[n], u1 = uh_s[n + 1];
                s0 += vn0 * tanh_approx(c[nt][0] + u0) + vn1 * tanh_approx(c[nt][1] + u1);
                s1 += vn0 * tanh_approx(c[nt][2] + u0) + vn1 * tanh_approx(c[nt][3] + u1);
            }
            s0 += __shfl_xor_sync(0xffffffffu, s0, 1);
            s0 += __shfl_xor_sync(0xffffffffu, s0, 2);
            s1 += __shfl_xor_sync(0xffffffffu, s1, 1);
            s1 += __shfl_xor_sync(0xffffffffu, s1, 2);
            if ((lane & 3) == 0) {
                int r = wy * 16 + qid;
                epi[wx * 128 + r]     = s0;
                epi[wx * 128 + r + 8] = s1;
            }
        }
        __syncthreads();

        // ---- tile softmax stats: raw score out, tile max, w = exp(s-m), tile sum
        float sv = 0.f;
        if (tid < 128) {
            sv = epi[tid] + epi[128 + tid];
            scores[(size_t)T * 128 + tid] = sv;
            float m = sv;
#pragma unroll
            for (int msk = 16; msk; msk >>= 1) m = fmaxf(m, __shfl_xor_sync(0xffffffffu, m, msk));
            if (lane == 0) red[wid] = m;
        }
        __syncthreads();
        float mt = fmaxf(fmaxf(red[0], red[1]), fmaxf(red[2], red[3]));
        if (tid < 128) {
            float w = __expf(sv - mt);
            swm[tid] = w;
#pragma unroll
            for (int msk = 16; msk; msk >>= 1) w += __shfl_xor_sync(0xffffffffu, w, msk);
            if (lane == 0) red[4 + wid] = w;
        }
        __syncthreads();
        if (tid == 0) {
            g_tmax[T] = mt;
            g_tsum[T] = red[4] + red[5] + red[6] + red[7];
        }

        // ---- partial context from resident A tiles: cpart[h] = sum_t w[t]*(hi+lo)
        {
            int h = tid & 127;
            int q = tid >> 7;                  // 32 timesteps per quarter
            const char* pAhi = sm + OFF_AHI + (q * 32) * RSTR + h * 2;
            const char* pAlo = sm + OFF_ALO + (q * 32) * RSTR + h * 2;
            float acc = 0.f;
#pragma unroll 8
            for (int t = 0; t < 32; ++t) {
                float ev = __bfloat162float(*(const __nv_bfloat16*)(pAhi + t * RSTR))
                         + __bfloat162float(*(const __nv_bfloat16*)(pAlo + t * RSTR));
                acc = fmaf(swm[q * 32 + t], ev, acc);
            }
            cp[q * 128 + h] = acc;
        }
        __syncthreads();
        if (tid < 128)
            g_cpart[(size_t)T * 128 + tid] = cp[tid] + cp[128 + tid] + cp[256 + tid] + cp[384 + tid];

        T = Tn;
        valid = nvalid;
    }
}

// ---------------- batch stats helper (warp 0 computes mm, inv) ----------------
__device__ __forceinline__ void batch_stats(int b, int tid, float* s_out) {
    if (tid < 32) {
        float m0 = g_tmax[b * TPB + tid], m1 = g_tmax[b * TPB + 32 + tid];
        float mm = fmaxf(m0, m1);
#pragma unroll
        for (int msk = 16; msk; msk >>= 1) mm = fmaxf(mm, __shfl_xor_sync(0xffffffffu, mm, msk));
        float s = g_tsum[b * TPB + tid] * __expf(m0 - mm)
                + g_tsum[b * TPB + 32 + tid] * __expf(m1 - mm);
#pragma unroll
        for (int msk = 16; msk; msk >>= 1) s += __shfl_xor_sync(0xffffffffu, s, msk);
        if (tid == 0) { s_out[0] = mm; s_out[1] = 1.f / s; }
    }
}

// ---------------- K4: e = exp(s - mm) * inv (float4, stats recomputed per block) ----------------
__global__ void k4_e(float* __restrict__ e_out) {
    __shared__ float st[2];
    int b = blockIdx.x >> 3, tid = threadIdx.x;
    batch_stats(b, tid, st);
    __syncthreads();
    float mm = st[0], inv = st[1];
    float4* p = (float4*)(e_out + (size_t)b * TE_ + (blockIdx.x & 7) * 1024) + tid;
    float4 v = *p;
    v.x = __expf(v.x - mm) * inv;
    v.y = __expf(v.y - mm) * inv;
    v.z = __expf(v.z - mm) * inv;
    v.w = __expf(v.w - mm) * inv;
    *p = v;
}

// ---------------- K5: rescale + reduce partial contexts ----------------
__global__ void k5_ctx(float* __restrict__ c_out) {
    __shared__ float st[2];
    __shared__ float sc[TPB];
    int b = blockIdx.x, tid = threadIdx.x;     // 128 threads
    batch_stats(b, tid, st);
    __syncthreads();
    if (tid < TPB) sc[tid] = __expf(g_tmax[b * TPB + tid] - st[0]);
    __syncthreads();
    float s = 0.f;
#pragma unroll
    for (int ti = 0; ti < TPB; ++ti)
        s += g_cpart[(size_t)(b * TPB + ti) * 128 + tid] * sc[ti];
    c_out[b * H_ + tid] = s * st[1];
}

// ---------------- launch ----------------
extern "C" void kernel_launch(void* const* d_in, const int* in_sizes, int n_in,
                              void* d_out, int out_size) {
    const float* enc = (const float*)d_in[0];
    const float* dec = (const float*)d_in[1];
    const float* W   = (const float*)d_in[2];
    const float* U   = (const float*)d_in[3];
    const float* V   = (const float*)d_in[4];

    float* out   = (float*)d_out;
    float* e_out = out;                        // [B, TE]
    float* c_out = out + (size_t)B_ * TE_;     // [B, H]

    static int s_grid = 0;
    if (!s_grid) {
        int dev = 0, sms = 148;
        cudaGetDevice(&dev);
        cudaDeviceGetAttribute(&sms, cudaDevAttrMultiProcessorCount, dev);
        cudaFuncSetAttribute(k2_scores, cudaFuncAttributeMaxDynamicSharedMemorySize, K2_SMEM);
        s_grid = sms > 0 ? sms : 148;
        if (s_grid > NTILE) s_grid = NTILE;
    }

    k01_prep<<<80, 256>>>(W, dec, U);
    k2_scores<<<s_grid, 512, K2_SMEM>>>(enc, V, e_out);
    k4_e<<<256, 256>>>(e_out);
    k5_ctx<<<B_, 128>>>(c_out);
}